// round 13
// baseline (speedup 1.0000x reference)
#include <cuda_runtime.h>
#include <cuda_fp16.h>

#define DD 128
#define MAXN 40000

// ---------------- device scratch (allocation-free rule) ----------------
__device__ float g_Ah[MAXN * DD];
// fp16 interleaved src-side table: per node 32 blocks of {Dh[4] (incl bc+bd), Bh[4] (incl bb)}
__device__ __align__(16) __half g_DB[MAXN * 2 * DD];
__device__ __align__(16) __half g_Eh16[MAXN * DD];   // incl be
// interleaved num/den: per node 32 blocks of {num[4], den[4]}
__device__ float g_nd[MAXN * 2 * DD];
// 5 transposed fp16 weights, pre-swizzled (blocked layout below)
__device__ __align__(16) unsigned char g_Wh[5 * 32768];

// ---------------- smem layouts ----------------
// edge: W 32KB | A 16KB (64x128 fp16) | C 16KB (64x128 fp16) | idx 0.5KB -> 66048B, 3 CTAs/SM
#define ESM_W 0
#define ESM_A 32768
#define ESM_C 49152
#define ESM_I 65536
#define ESM_REQ 66048
// node: W 32KB | A 32KB
#define NSM_W 0
#define NSM_A 32768
#define NSM_REQ 65536

// ---------------- helpers ----------------
static __device__ __forceinline__ unsigned smem_u32(const void* p) {
    unsigned a;
    asm("{ .reg .u64 t; cvta.to.shared.u64 t, %1; cvt.u32.u64 %0, t; }" : "=r"(a) : "l"(p));
    return a;
}
// blocked swizzled layout for a 128-row x 128-halfword-col tile (ldmatrix source)
static __device__ __forceinline__ unsigned bsw(int row, int col) {
    unsigned off = (unsigned)((((row >> 3) + ((col >> 6) << 4)) << 10)
                              + ((row & 7) << 7) + ((col & 63) << 1));
    return off ^ ((off >> 3) & 0x70);
}
// blocked swizzled layout for a 64-row x 128-halfword-col tile (edge A)
static __device__ __forceinline__ unsigned bswA64(int row, int col) {
    unsigned off = (unsigned)((((row >> 3) + ((col >> 6) << 3)) << 10)
                              + ((row & 7) << 7) + ((col & 63) << 1));
    return off ^ ((off >> 3) & 0x70);
}
// C staging swizzle (half-index units): 64 rows x 128 halves, 8-half blocks XOR'd by row
static __device__ __forceinline__ int csw16(int r, int c) {
    return r * 128 + (c ^ ((r & 7) << 3));
}
static __device__ __forceinline__ void ldsm_x4(unsigned& r0, unsigned& r1,
                                               unsigned& r2, unsigned& r3, unsigned addr) {
    asm volatile("ldmatrix.sync.aligned.m8n8.x4.shared.b16 {%0,%1,%2,%3}, [%4];"
                 : "=r"(r0), "=r"(r1), "=r"(r2), "=r"(r3) : "r"(addr));
}
static __device__ __forceinline__ void mma_fp16(float c[4], unsigned a0, unsigned a1,
                                                unsigned a2, unsigned a3,
                                                unsigned b0, unsigned b1) {
    asm volatile("mma.sync.aligned.m16n8k16.row.col.f32.f16.f16.f32 "
                 "{%0,%1,%2,%3}, {%4,%5,%6,%7}, {%8,%9}, {%0,%1,%2,%3};"
                 : "+f"(c[0]), "+f"(c[1]), "+f"(c[2]), "+f"(c[3])
                 : "r"(a0), "r"(a1), "r"(a2), "r"(a3), "r"(b0), "r"(b1));
}
static __device__ __forceinline__ void red_add_v4(float* p, float4 v) {
    asm volatile("red.global.add.v4.f32 [%0], {%1,%2,%3,%4};"
                 :: "l"(p), "f"(v.x), "f"(v.y), "f"(v.z), "f"(v.w) : "memory");
}
static __device__ __forceinline__ float2 h2f(unsigned u) {
    return __half22float2(*(__half2*)&u);
}
// sigmoid(x) = 0.5 * tanh(x/2) + 0.5  -- single MUFU.TANH
static __device__ __forceinline__ float sigmoid_tanh(float x) {
    float t;
    asm("tanh.approx.f32 %0, %1;" : "=f"(t) : "f"(x * 0.5f));
    return fmaf(0.5f, t, 0.5f);
}

// fp32 -> fp16 conversion into swizzled smem, 128-row tile (node kernel). 256 threads.
template<bool SCALE>
static __device__ __forceinline__ void load_convert_A128(
        const float* __restrict__ X, const float* __restrict__ norm,
        int row0, int M, unsigned char* A) {
    int t = threadIdx.x;
    #pragma unroll
    for (int it = 0; it < 8; it++) {               // 2048 8-col chunks / 256 thr
        int f = t + it * 256;
        int row = f >> 4;
        int col0 = (f & 15) * 8;
        int gr = row0 + row;
        float4 v0 = make_float4(0.f, 0.f, 0.f, 0.f);
        float4 v1 = v0;
        if (gr < M) {
            const float4* p = (const float4*)(X + (size_t)gr * DD + col0);
            v0 = __ldg(p);
            v1 = __ldg(p + 1);
            if (SCALE) {
                float nm = __ldg(norm + gr);
                v0.x *= nm; v0.y *= nm; v0.z *= nm; v0.w *= nm;
                v1.x *= nm; v1.y *= nm; v1.z *= nm; v1.w *= nm;
            }
        }
        uint4 pk;
        asm("cvt.rn.f16x2.f32 %0, %1, %2;" : "=r"(pk.x) : "f"(v0.y), "f"(v0.x));
        asm("cvt.rn.f16x2.f32 %0, %1, %2;" : "=r"(pk.y) : "f"(v0.w), "f"(v0.z));
        asm("cvt.rn.f16x2.f32 %0, %1, %2;" : "=r"(pk.z) : "f"(v1.y), "f"(v1.x));
        asm("cvt.rn.f16x2.f32 %0, %1, %2;" : "=r"(pk.w) : "f"(v1.w), "f"(v1.z));
        *(uint4*)(A + bsw(row, col0)) = pk;
    }
}

// fp32 -> fp16 conversion, 64-row tile (edge kernel), streaming loads. 256 threads.
static __device__ __forceinline__ void load_convert_A64(
        const float* __restrict__ X, int row0, int M, unsigned char* A) {
    int t = threadIdx.x;
    #pragma unroll
    for (int it = 0; it < 4; it++) {               // 1024 8-col chunks / 256 thr
        int f = t + it * 256;
        int row = f >> 4;
        int col0 = (f & 15) * 8;
        int gr = row0 + row;
        float4 v0 = make_float4(0.f, 0.f, 0.f, 0.f);
        float4 v1 = v0;
        if (gr < M) {
            const float4* p = (const float4*)(X + (size_t)gr * DD + col0);
            v0 = __ldcs(p);
            v1 = __ldcs(p + 1);
        }
        uint4 pk;
        asm("cvt.rn.f16x2.f32 %0, %1, %2;" : "=r"(pk.x) : "f"(v0.y), "f"(v0.x));
        asm("cvt.rn.f16x2.f32 %0, %1, %2;" : "=r"(pk.y) : "f"(v0.w), "f"(v0.z));
        asm("cvt.rn.f16x2.f32 %0, %1, %2;" : "=r"(pk.z) : "f"(v1.y), "f"(v1.x));
        asm("cvt.rn.f16x2.f32 %0, %1, %2;" : "=r"(pk.w) : "f"(v1.w), "f"(v1.z));
        *(uint4*)(A + bswA64(row, col0)) = pk;
    }
}

// ---------------- node GEMM helper: 64-col half, warp = 16 rows x 64 cols ----------------
static __device__ __forceinline__ void gemm_fp16_half(
        const unsigned char* smA, const unsigned char* smW, int half, float acc[8][4]) {
    unsigned aB = smem_u32(smA), wB = smem_u32(smW);
    int tid = threadIdx.x, lane = tid & 31, w = tid >> 5;
    int lr = lane & 7, m = lane >> 3;
    int aRow = w * 16 + (m & 1) * 8 + lr;
    int aCol = (m >> 1) * 8;
    int bRow = half * 64 + (m >> 1) * 8 + lr;
    int bCol = (m & 1) * 8;

    #pragma unroll
    for (int n8 = 0; n8 < 8; n8++)
        #pragma unroll
        for (int q = 0; q < 4; q++) acc[n8][q] = 0.f;

    #pragma unroll
    for (int kk = 0; kk < 8; kk++) {
        int k0 = kk * 16;
        unsigned a0, a1, a2, a3;
        ldsm_x4(a0, a1, a2, a3, aB + bsw(aRow, k0 + aCol));
        #pragma unroll
        for (int nt = 0; nt < 4; nt++) {
            unsigned b0, b1, b2, b3;
            ldsm_x4(b0, b1, b2, b3, wB + bsw(bRow + nt * 16, k0 + bCol));
            mma_fp16(acc[nt * 2],     a0, a1, a2, a3, b0, b1);
            mma_fp16(acc[nt * 2 + 1], a0, a1, a2, a3, b2, b3);
        }
    }
}

// ---------------- edge GEMM: single pass, 64x128 tile, warp(wm,wn) = 16r x 64c ----------------
static __device__ __forceinline__ void gemm_fp16_64(
        const unsigned char* smA, const unsigned char* smW, float acc[8][4]) {
    unsigned aB = smem_u32(smA), wB = smem_u32(smW);
    int tid = threadIdx.x, lane = tid & 31, w = tid >> 5;
    int wm = w & 3, wn = w >> 2;
    int lr = lane & 7, m = lane >> 3;
    int aRow = wm * 16 + (m & 1) * 8 + lr;
    int aCol = (m >> 1) * 8;
    int bRow = wn * 64 + (m >> 1) * 8 + lr;
    int bCol = (m & 1) * 8;

    #pragma unroll
    for (int n8 = 0; n8 < 8; n8++)
        #pragma unroll
        for (int q = 0; q < 4; q++) acc[n8][q] = 0.f;

    #pragma unroll
    for (int kk = 0; kk < 8; kk++) {
        int k0 = kk * 16;
        unsigned a0, a1, a2, a3;
        ldsm_x4(a0, a1, a2, a3, aB + bswA64(aRow, k0 + aCol));
        #pragma unroll
        for (int nt = 0; nt < 4; nt++) {
            unsigned b0, b1, b2, b3;
            ldsm_x4(b0, b1, b2, b3, wB + bsw(bRow + nt * 16, k0 + bCol));
            mma_fp16(acc[nt * 2],     a0, a1, a2, a3, b0, b1);
            mma_fp16(acc[nt * 2 + 1], a0, a1, a2, a3, b2, b3);
        }
    }
}

// ---------------- prep: transpose/convert/swizzle weights ----------------
__global__ void prep_kernel(const float* __restrict__ Wa, const float* __restrict__ Wb,
                            const float* __restrict__ Wc, const float* __restrict__ Wd,
                            const float* __restrict__ We) {
    int idx = blockIdx.x * blockDim.x + threadIdx.x;
    if (idx < 5 * 16384) {
        int mm = idx >> 14;
        int rem = idx & 16383;
        int n = rem >> 7, k = rem & 127;
        const float* W = (mm == 0) ? Wa : (mm == 1) ? Wb : (mm == 2) ? Wc : (mm == 3) ? Wd : We;
        float v = W[k * DD + n];                 // transpose: Wt[n][k] = W[k][n]
        *(__half*)(g_Wh + mm * 32768 + bsw(n, k)) = __float2half_rn(v);
    }
}

__global__ void zero_kernel(int Nn) {
    int idx = blockIdx.x * blockDim.x + threadIdx.x;   // float4 index
    int total = Nn * (2 * DD / 4);
    if (idx < total)
        ((float4*)g_nd)[idx] = make_float4(0.f, 0.f, 0.f, 0.f);
}

// ---------------- node GEMMs ----------------
__global__ __launch_bounds__(256, 2) void node_mma_kernel(
        const float* __restrict__ h, const float* __restrict__ norm,
        const float* __restrict__ ba, const float* __restrict__ bb,
        const float* __restrict__ bd, const float* __restrict__ be,
        const float* __restrict__ bc, int M) {
    extern __shared__ unsigned char sm[];
    int tid = threadIdx.x;
    int y = blockIdx.y;
    int widx = (y == 0) ? 0 : (y == 1) ? 1 : (y == 2) ? 3 : 4;   // a,b,d,e
    const float* bias = (y == 0) ? ba   : (y == 1) ? bb   : (y == 2) ? bd   : be;
    const float* bias2 = (y == 2) ? bc : nullptr;     // fold bc into Dh
    int row0 = blockIdx.x * 128;

    {
        const uint4* s = (const uint4*)(g_Wh + widx * 32768);
        uint4* d = (uint4*)(sm + NSM_W);
        #pragma unroll
        for (int i = tid; i < 2048; i += 256) d[i] = __ldg(s + i);
    }
    load_convert_A128<true>(h, norm, row0, M, sm + NSM_A);
    __syncthreads();

    int lane = tid & 31, w = tid >> 5;
    int rbase = row0 + w * 16 + (lane >> 2);
    int cp = 2 * (lane & 3);

    #pragma unroll
    for (int half = 0; half < 2; half++) {
        float acc[8][4];
        gemm_fp16_half(sm + NSM_A, sm + NSM_W, half, acc);
        #pragma unroll
        for (int n8 = 0; n8 < 8; n8++) {
            int c = half * 64 + n8 * 8 + cp;
            float2 bv = __ldg((const float2*)(bias + c));
            if (bias2) {
                float2 b2 = __ldg((const float2*)(bias2 + c));
                bv.x += b2.x; bv.y += b2.y;
            }
            #pragma unroll
            for (int rr = 0; rr < 2; rr++) {
                int r = rbase + rr * 8;
                if (r < M) {
                    float2 v = make_float2(acc[n8][rr * 2] + bv.x, acc[n8][rr * 2 + 1] + bv.y);
                    if (y == 0) {
                        *(float2*)(g_Ah + (size_t)r * DD + c) = v;
                    } else if (y == 3) {
                        *(__half2*)(g_Eh16 + (size_t)r * DD + c) = __floats2half2_rn(v.x, v.y);
                    } else {
                        size_t base = (size_t)r * (2 * DD) + 8 * (c >> 2) + (c & 3)
                                    + (y == 1 ? 4 : 0);
                        *(__half2*)(g_DB + base) = __floats2half2_rn(v.x, v.y);
                    }
                }
            }
        }
    }
}

// ---------------- edge kernel: 64-edge tile, 3 CTAs/SM, single-pass GEMM ----------------
__global__ __launch_bounds__(256, 3) void edge_mma_kernel(
        const float* __restrict__ e,
        const int* __restrict__ src, const int* __restrict__ dst,
        float* __restrict__ out_e, int E) {
    extern __shared__ unsigned char sm[];
    int tid = threadIdx.x;
    int tile = blockIdx.x;
    int row0 = tile * 64;

    {   // Wc (index 2)
        const uint4* s = (const uint4*)(g_Wh + 2 * 32768);
        uint4* d = (uint4*)(sm + ESM_W);
        #pragma unroll
        for (int i = tid; i < 2048; i += 256) d[i] = __ldg(s + i);
    }
    // stage src/dst pairs for the tile
    if (tid < 64) {
        int er = row0 + tid;
        int2 sd = (er < E) ? make_int2(__ldg(src + er), __ldg(dst + er))
                           : make_int2(0, 0);
        ((int2*)(sm + ESM_I))[tid] = sd;
    }
    load_convert_A64(e, row0, E, sm + ESM_A);
    __syncthreads();

    int lane = tid & 31, w = tid >> 5;
    int wm = w & 3, wn = w >> 2;
    __half* Ch = (__half*)(sm + ESM_C);
    const int2* sidx = (const int2*)(sm + ESM_I);

    // GEMM: single pass over all 128 cols
    float acc[8][4];
    gemm_fp16_64(sm + ESM_A, sm + ESM_W, acc);

    // stage C as fp16 (conflict-free XOR swizzle)
    {
        int sr = wm * 16 + (lane >> 2);
        int cb0 = wn * 64 + 2 * (lane & 3);
        #pragma unroll
        for (int n8 = 0; n8 < 8; n8++) {
            int c = cb0 + n8 * 8;
            *(__half2*)(Ch + csw16(sr, c))     = __floats2half2_rn(acc[n8][0], acc[n8][1]);
            *(__half2*)(Ch + csw16(sr + 8, c)) = __floats2half2_rn(acc[n8][2], acc[n8][3]);
        }
    }
    __syncthreads();

    // epilogue: warp w handles edges w*8 .. w*8+7; 32 lanes cover 128 cols (float4 each)
    int j = lane;                    // col block: cols 4j..4j+3
    int cc = 4 * j;

    int2 sd = sidx[w * 8];
    uint4 pdb = __ldg((const uint4*)(g_DB + (size_t)sd.x * (2 * DD) + 8 * j));
    uint2 peh = __ldg((const uint2*)(g_Eh16 + (size_t)sd.y * DD + cc));

    #pragma unroll
    for (int k = 0; k < 8; k++) {
        int lr = w * 8 + k;
        int er = row0 + lr;
        uint4 db = pdb;
        uint2 eh = peh;
        int dcur = sd.y;
        if (k < 7) {
            sd = sidx[lr + 1];
            pdb = __ldg((const uint4*)(g_DB + (size_t)sd.x * (2 * DD) + 8 * j));
            peh = __ldg((const uint2*)(g_Eh16 + (size_t)sd.y * DD + cc));
        }
        if (er < E) {
            uint2 cu = *(uint2*)(Ch + csw16(lr, cc));
            float2 c01 = h2f(cu.x), c23 = h2f(cu.y);
            float2 d01 = h2f(db.x), d23 = h2f(db.y);
            float2 b01 = h2f(db.z), b23 = h2f(db.w);
            float2 e01 = h2f(eh.x), e23 = h2f(eh.y);
            float4 x;
            x.x = c01.x + d01.x + e01.x;    // Dh includes bd + bc
            x.y = c01.y + d01.y + e01.y;
            x.z = c23.x + d23.x + e23.x;
            x.w = c23.y + d23.y + e23.y;
            __stcs((float4*)(out_e + (size_t)er * DD + cc), x);
            float4 sg;
            sg.x = sigmoid_tanh(x.x);
            sg.y = sigmoid_tanh(x.y);
            sg.z = sigmoid_tanh(x.z);
            sg.w = sigmoid_tanh(x.w);
            float4 nm4 = make_float4(sg.x * b01.x, sg.y * b01.y,
                                     sg.z * b23.x, sg.w * b23.y);
            float* ndp = g_nd + (size_t)dcur * (2 * DD) + 8 * j;
            red_add_v4(ndp, nm4);
            red_add_v4(ndp + 4, sg);
        }
    }
}

// ---------------- finalize (deg>0 <=> den>0, sigmoids strictly positive) ----------------
__global__ void finalize_kernel(const float* __restrict__ h,
                                const float* __restrict__ norm,
                                float* __restrict__ out_h, int Nn) {
    int idx = blockIdx.x * blockDim.x + threadIdx.x;   // float4-block index
    int total = Nn * (DD / 4);
    if (idx >= total) return;
    int node = idx >> 5;
    int jj = idx & 31;
    float nm = __ldg(norm + node);
    const float* ndp = g_nd + (size_t)node * (2 * DD) + 8 * jj;
    float4 nu = *(const float4*)(ndp);
    float4 de = *(const float4*)(ndp + 4);
    float4 r;
    if (de.x > 0.f) {
        float4 a = ((const float4*)g_Ah)[idx];
        r.x = (a.x + nu.x / (de.x + 1e-6f)) * nm;
        r.y = (a.y + nu.y / (de.y + 1e-6f)) * nm;
        r.z = (a.z + nu.z / (de.z + 1e-6f)) * nm;
        r.w = (a.w + nu.w / (de.w + 1e-6f)) * nm;
    } else {
        float4 hh = *(const float4*)(h + (size_t)idx * 4);
        float sc = nm * nm;
        r = make_float4(hh.x * sc, hh.y * sc, hh.z * sc, hh.w * sc);
    }
    ((float4*)out_h)[idx] = r;
}

// ---------------- launch ----------------
extern "C" void kernel_launch(void* const* d_in, const int* in_sizes, int n_in,
                              void* d_out, int out_size) {
    const float* h    = (const float*)d_in[0];
    const float* e    = (const float*)d_in[1];
    const float* norm = (const float*)d_in[2];
    const int*   src  = (const int*)d_in[3];
    const int*   dst  = (const int*)d_in[4];
    const float* Wa = (const float*)d_in[5],  *ba = (const float*)d_in[6];
    const float* Wb = (const float*)d_in[7],  *bb = (const float*)d_in[8];
    const float* Wc = (const float*)d_in[9],  *bc = (const float*)d_in[10];
    const float* Wd = (const float*)d_in[11], *bd = (const float*)d_in[12];
    const float* We = (const float*)d_in[13], *be = (const float*)d_in[14];

    int Nn = in_sizes[0] / DD;   // 40000
    int Ee = in_sizes[3];        // 600000

    float* out_h = (float*)d_out;
    float* out_e = out_h + (size_t)Nn * DD;

    cudaFuncSetAttribute(node_mma_kernel, cudaFuncAttributeMaxDynamicSharedMemorySize, NSM_REQ);
    cudaFuncSetAttribute(edge_mma_kernel, cudaFuncAttributeMaxDynamicSharedMemorySize, ESM_REQ);

    // launch order: edge kernel is the 4th launch (ncu captures #4)
    prep_kernel<<<(5 * 16384 + 255) / 256, 256>>>(Wa, Wb, Wc, Wd, We);

    zero_kernel<<<(Nn * (2 * DD / 4) + 255) / 256, 256>>>(Nn);

    dim3 ngrid((Nn + 127) / 128, 4);
    node_mma_kernel<<<ngrid, 256, NSM_REQ>>>(h, norm, ba, bb, bd, be, bc, Nn);

    edge_mma_kernel<<<(Ee + 63) / 64, 256, ESM_REQ>>>(e, src, dst, out_e, Ee);

    finalize_kernel<<<(Nn * (DD / 4) + 255) / 256, 256>>>(h, norm, out_h, Nn);
}

// round 14
// speedup vs baseline: 1.0639x; 1.0639x over previous
#include <cuda_runtime.h>
#include <cuda_fp16.h>

#define DD 128
#define MAXN 40000
#define MAXE 600000

// ---------------- device scratch (allocation-free rule) ----------------
__device__ float g_Ah[MAXN * DD];
// fp16 interleaved src-side table: per node 32 blocks of {Dh[4] (incl bc+bd), Bh[4] (incl bb)}
__device__ __align__(16) __half g_DB[MAXN * 2 * DD];
__device__ __align__(16) __half g_Eh16[MAXN * DD];   // incl be
// interleaved num/den: per node 32 blocks of {num[4], den[4]}
__device__ float g_nd[MAXN * 2 * DD];
// 5 transposed fp16 weights, pre-swizzled (blocked layout below)
__device__ __align__(16) unsigned char g_Wh[5 * 32768];
// counting sort by dst
__device__ int g_cnt[MAXN];
__device__ int g_cur[MAXN];
__device__ int g_perm[MAXE];

// ---------------- smem layouts ----------------
// edge: W 32KB | A 32KB | C 32KB (128x128 fp16) | pe 512B | sd 1KB -> 99840B, 2 CTAs/SM
#define ESM_W 0
#define ESM_A 32768
#define ESM_C 65536
#define ESM_PE 98304
#define ESM_SD 98816
#define ESM_REQ 99840
// node: W 32KB | A 32KB
#define NSM_W 0
#define NSM_A 32768
#define NSM_REQ 65536

// ---------------- helpers ----------------
static __device__ __forceinline__ unsigned smem_u32(const void* p) {
    unsigned a;
    asm("{ .reg .u64 t; cvta.to.shared.u64 t, %1; cvt.u32.u64 %0, t; }" : "=r"(a) : "l"(p));
    return a;
}
// blocked swizzled layout for a 128-row x 128-halfword-col tile (ldmatrix source)
static __device__ __forceinline__ unsigned bsw(int row, int col) {
    unsigned off = (unsigned)((((row >> 3) + ((col >> 6) << 4)) << 10)
                              + ((row & 7) << 7) + ((col & 63) << 1));
    return off ^ ((off >> 3) & 0x70);
}
// C staging swizzle (half-index units): 128 rows x 128 halves, 8-half blocks XOR'd by row
static __device__ __forceinline__ int csw16(int r, int c) {
    return r * 128 + (c ^ ((r & 7) << 3));
}
static __device__ __forceinline__ void ldsm_x4(unsigned& r0, unsigned& r1,
                                               unsigned& r2, unsigned& r3, unsigned addr) {
    asm volatile("ldmatrix.sync.aligned.m8n8.x4.shared.b16 {%0,%1,%2,%3}, [%4];"
                 : "=r"(r0), "=r"(r1), "=r"(r2), "=r"(r3) : "r"(addr));
}
static __device__ __forceinline__ void mma_fp16(float c[4], unsigned a0, unsigned a1,
                                                unsigned a2, unsigned a3,
                                                unsigned b0, unsigned b1) {
    asm volatile("mma.sync.aligned.m16n8k16.row.col.f32.f16.f16.f32 "
                 "{%0,%1,%2,%3}, {%4,%5,%6,%7}, {%8,%9}, {%0,%1,%2,%3};"
                 : "+f"(c[0]), "+f"(c[1]), "+f"(c[2]), "+f"(c[3])
                 : "r"(a0), "r"(a1), "r"(a2), "r"(a3), "r"(b0), "r"(b1));
}
static __device__ __forceinline__ void red_add_v4(float* p, float4 v) {
    asm volatile("red.global.add.v4.f32 [%0], {%1,%2,%3,%4};"
                 :: "l"(p), "f"(v.x), "f"(v.y), "f"(v.z), "f"(v.w) : "memory");
}
static __device__ __forceinline__ float2 h2f(unsigned u) {
    return __half22float2(*(__half2*)&u);
}
// sigmoid(x) = 0.5 * tanh(x/2) + 0.5  -- single MUFU.TANH
static __device__ __forceinline__ float sigmoid_tanh(float x) {
    float t;
    asm("tanh.approx.f32 %0, %1;" : "=f"(t) : "f"(x * 0.5f));
    return fmaf(0.5f, t, 0.5f);
}

// fp32 -> fp16 into swizzled smem, 128-row tile, direct rows (node kernel). 256 threads.
template<bool SCALE>
static __device__ __forceinline__ void load_convert_A128(
        const float* __restrict__ X, const float* __restrict__ norm,
        int row0, int M, unsigned char* A) {
    int t = threadIdx.x;
    #pragma unroll
    for (int it = 0; it < 8; it++) {
        int f = t + it * 256;
        int row = f >> 4;
        int col0 = (f & 15) * 8;
        int gr = row0 + row;
        float4 v0 = make_float4(0.f, 0.f, 0.f, 0.f);
        float4 v1 = v0;
        if (gr < M) {
            const float4* p = (const float4*)(X + (size_t)gr * DD + col0);
            v0 = __ldg(p);
            v1 = __ldg(p + 1);
            if (SCALE) {
                float nm = __ldg(norm + gr);
                v0.x *= nm; v0.y *= nm; v0.z *= nm; v0.w *= nm;
                v1.x *= nm; v1.y *= nm; v1.z *= nm; v1.w *= nm;
            }
        }
        uint4 pk;
        asm("cvt.rn.f16x2.f32 %0, %1, %2;" : "=r"(pk.x) : "f"(v0.y), "f"(v0.x));
        asm("cvt.rn.f16x2.f32 %0, %1, %2;" : "=r"(pk.y) : "f"(v0.w), "f"(v0.z));
        asm("cvt.rn.f16x2.f32 %0, %1, %2;" : "=r"(pk.z) : "f"(v1.y), "f"(v1.x));
        asm("cvt.rn.f16x2.f32 %0, %1, %2;" : "=r"(pk.w) : "f"(v1.w), "f"(v1.z));
        *(uint4*)(A + bsw(row, col0)) = pk;
    }
}

// fp32 -> fp16 into swizzled smem, 128-row tile, perm-indirected rows (edge kernel).
static __device__ __forceinline__ void load_convert_Aperm(
        const float* __restrict__ X, const int* __restrict__ perm,
        int row0, int M, unsigned char* A) {
    int t = threadIdx.x;
    #pragma unroll
    for (int it = 0; it < 8; it++) {
        int f = t + it * 256;
        int row = f >> 4;
        int col0 = (f & 15) * 8;
        int spos = row0 + row;
        float4 v0 = make_float4(0.f, 0.f, 0.f, 0.f);
        float4 v1 = v0;
        if (spos < M) {
            int pe = __ldg(perm + spos);
            const float4* p = (const float4*)(X + (size_t)pe * DD + col0);
            v0 = __ldcs(p);
            v1 = __ldcs(p + 1);
        }
        uint4 pk;
        asm("cvt.rn.f16x2.f32 %0, %1, %2;" : "=r"(pk.x) : "f"(v0.y), "f"(v0.x));
        asm("cvt.rn.f16x2.f32 %0, %1, %2;" : "=r"(pk.y) : "f"(v0.w), "f"(v0.z));
        asm("cvt.rn.f16x2.f32 %0, %1, %2;" : "=r"(pk.z) : "f"(v1.y), "f"(v1.x));
        asm("cvt.rn.f16x2.f32 %0, %1, %2;" : "=r"(pk.w) : "f"(v1.w), "f"(v1.z));
        *(uint4*)(A + bsw(row, col0)) = pk;
    }
}

// ---------------- fp16 GEMM, 64-col half: 8 warps, warp = 16 rows x 64 cols ----------------
static __device__ __forceinline__ void gemm_fp16_half(
        const unsigned char* smA, const unsigned char* smW, int half, float acc[8][4]) {
    unsigned aB = smem_u32(smA), wB = smem_u32(smW);
    int tid = threadIdx.x, lane = tid & 31, w = tid >> 5;
    int lr = lane & 7, m = lane >> 3;
    int aRow = w * 16 + (m & 1) * 8 + lr;
    int aCol = (m >> 1) * 8;
    int bRow = half * 64 + (m >> 1) * 8 + lr;
    int bCol = (m & 1) * 8;

    #pragma unroll
    for (int n8 = 0; n8 < 8; n8++)
        #pragma unroll
        for (int q = 0; q < 4; q++) acc[n8][q] = 0.f;

    #pragma unroll
    for (int kk = 0; kk < 8; kk++) {
        int k0 = kk * 16;
        unsigned a0, a1, a2, a3;
        ldsm_x4(a0, a1, a2, a3, aB + bsw(aRow, k0 + aCol));
        #pragma unroll
        for (int nt = 0; nt < 4; nt++) {
            unsigned b0, b1, b2, b3;
            ldsm_x4(b0, b1, b2, b3, wB + bsw(bRow + nt * 16, k0 + bCol));
            mma_fp16(acc[nt * 2],     a0, a1, a2, a3, b0, b1);
            mma_fp16(acc[nt * 2 + 1], a0, a1, a2, a3, b2, b3);
        }
    }
}

// ---------------- prep: weights + zero dst histogram ----------------
__global__ void prep_kernel(const float* __restrict__ Wa, const float* __restrict__ Wb,
                            const float* __restrict__ Wc, const float* __restrict__ Wd,
                            const float* __restrict__ We, int Nn) {
    int idx = blockIdx.x * blockDim.x + threadIdx.x;
    if (idx < Nn) g_cnt[idx] = 0;
    if (idx < 5 * 16384) {
        int mm = idx >> 14;
        int rem = idx & 16383;
        int n = rem >> 7, k = rem & 127;
        const float* W = (mm == 0) ? Wa : (mm == 1) ? Wb : (mm == 2) ? Wc : (mm == 3) ? Wd : We;
        float v = W[k * DD + n];                 // transpose: Wt[n][k] = W[k][n]
        *(__half*)(g_Wh + mm * 32768 + bsw(n, k)) = __float2half_rn(v);
    }
}

// ---------------- zero nd + histogram dst ----------------
__global__ void zero_hist_kernel(const int* __restrict__ dst, int Nn, int E) {
    int idx = blockIdx.x * blockDim.x + threadIdx.x;
    int total = Nn * (2 * DD / 4);
    if (idx < total)
        ((float4*)g_nd)[idx] = make_float4(0.f, 0.f, 0.f, 0.f);
    if (idx < E)
        atomicAdd(&g_cnt[__ldg(dst + idx)], 1);
}

__global__ void scan_kernel(int Nn) {
    __shared__ int ss[1024];
    const int CH = 40;                 // 1024*40 = 40960 >= Nn
    int t = threadIdx.x;
    int base = t * CH;
    int s = 0;
    for (int i = 0; i < CH; i++)
        s += (base + i < Nn) ? g_cnt[base + i] : 0;
    ss[t] = s;
    __syncthreads();
    for (int d = 1; d < 1024; d <<= 1) {
        int v = (t >= d) ? ss[t - d] : 0;
        __syncthreads();
        ss[t] += v;
        __syncthreads();
    }
    int run = ss[t] - s;               // exclusive prefix
    for (int i = 0; i < CH; i++) {
        if (base + i < Nn) {
            g_cur[base + i] = run;
            run += g_cnt[base + i];
        }
    }
}

__global__ void scatter_kernel(const int* __restrict__ dst, int E) {
    int idx = blockIdx.x * blockDim.x + threadIdx.x;
    if (idx < E) {
        int pos = atomicAdd(&g_cur[__ldg(dst + idx)], 1);
        g_perm[pos] = idx;
    }
}

// ---------------- node GEMMs ----------------
// y: 0 -> Ah (ba, fp32 linear), 1 -> Bh (bb, g_DB half, +4), 2 -> Dh (bd+bc, g_DB half, +0),
//    3 -> Eh (be, g_Eh16 half linear)
__global__ __launch_bounds__(256, 2) void node_mma_kernel(
        const float* __restrict__ h, const float* __restrict__ norm,
        const float* __restrict__ ba, const float* __restrict__ bb,
        const float* __restrict__ bd, const float* __restrict__ be,
        const float* __restrict__ bc, int M) {
    extern __shared__ unsigned char sm[];
    int tid = threadIdx.x;
    int y = blockIdx.y;
    int widx = (y == 0) ? 0 : (y == 1) ? 1 : (y == 2) ? 3 : 4;   // a,b,d,e
    const float* bias = (y == 0) ? ba   : (y == 1) ? bb   : (y == 2) ? bd   : be;
    const float* bias2 = (y == 2) ? bc : nullptr;     // fold bc into Dh
    int row0 = blockIdx.x * 128;

    {
        const uint4* s = (const uint4*)(g_Wh + widx * 32768);
        uint4* d = (uint4*)(sm + NSM_W);
        #pragma unroll
        for (int i = tid; i < 2048; i += 256) d[i] = __ldg(s + i);
    }
    load_convert_A128<true>(h, norm, row0, M, sm + NSM_A);
    __syncthreads();

    int lane = tid & 31, w = tid >> 5;
    int rbase = row0 + w * 16 + (lane >> 2);
    int cp = 2 * (lane & 3);

    #pragma unroll
    for (int half = 0; half < 2; half++) {
        float acc[8][4];
        gemm_fp16_half(sm + NSM_A, sm + NSM_W, half, acc);
        #pragma unroll
        for (int n8 = 0; n8 < 8; n8++) {
            int c = half * 64 + n8 * 8 + cp;
            float2 bv = __ldg((const float2*)(bias + c));
            if (bias2) {
                float2 b2 = __ldg((const float2*)(bias2 + c));
                bv.x += b2.x; bv.y += b2.y;
            }
            #pragma unroll
            for (int rr = 0; rr < 2; rr++) {
                int r = rbase + rr * 8;
                if (r < M) {
                    float2 v = make_float2(acc[n8][rr * 2] + bv.x, acc[n8][rr * 2 + 1] + bv.y);
                    if (y == 0) {
                        *(float2*)(g_Ah + (size_t)r * DD + c) = v;
                    } else if (y == 3) {
                        *(__half2*)(g_Eh16 + (size_t)r * DD + c) = __floats2half2_rn(v.x, v.y);
                    } else {
                        size_t base = (size_t)r * (2 * DD) + 8 * (c >> 2) + (c & 3)
                                    + (y == 1 ? 4 : 0);
                        *(__half2*)(g_DB + base) = __floats2half2_rn(v.x, v.y);
                    }
                }
            }
        }
    }
}

// ---------------- edge kernel: dst-sorted tile; run-accumulated reds ----------------
__global__ __launch_bounds__(256, 2) void edge_mma_kernel(
        const float* __restrict__ e,
        const int* __restrict__ src, const int* __restrict__ dst,
        float* __restrict__ out_e, int E) {
    extern __shared__ unsigned char sm[];
    int tid = threadIdx.x;
    int tile = blockIdx.x;
    int row0 = tile * 128;

    {   // Wc (index 2)
        const uint4* s = (const uint4*)(g_Wh + 2 * 32768);
        uint4* d = (uint4*)(sm + ESM_W);
        #pragma unroll
        for (int i = tid; i < 2048; i += 256) d[i] = __ldg(s + i);
    }
    // stage {perm, src, dst} for the tile's sorted positions
    if (tid < 128) {
        int spos = row0 + tid;
        int pe = 0; int2 sd = make_int2(0, -1);
        if (spos < E) {
            pe = __ldg(g_perm + spos);
            sd = make_int2(__ldg(src + pe), __ldg(dst + pe));
        }
        ((int*)(sm + ESM_PE))[tid] = pe;
        ((int2*)(sm + ESM_SD))[tid] = sd;
    }
    load_convert_Aperm(e, g_perm, row0, E, sm + ESM_A);
    __syncthreads();

    int lane = tid & 31, w = tid >> 5;
    __half* Ch = (__half*)(sm + ESM_C);
    const int*  pes = (const int*)(sm + ESM_PE);
    const int2* sds = (const int2*)(sm + ESM_SD);

    // GEMM both halves, staging fp16 C full tile
    {
        int sr = w * 16 + (lane >> 2);
        int cb = 2 * (lane & 3);
        #pragma unroll
        for (int half = 0; half < 2; half++) {
            float acc[8][4];
            gemm_fp16_half(sm + ESM_A, sm + ESM_W, half, acc);
            #pragma unroll
            for (int n8 = 0; n8 < 8; n8++) {
                int c = half * 64 + n8 * 8 + cb;
                *(__half2*)(Ch + csw16(sr, c))     = __floats2half2_rn(acc[n8][0], acc[n8][1]);
                *(__half2*)(Ch + csw16(sr + 8, c)) = __floats2half2_rn(acc[n8][2], acc[n8][3]);
            }
        }
    }
    __syncthreads();

    // epilogue: warp w owns 16 consecutive SORTED edges; 32 lanes cover 128 cols (float4)
    int j = lane;
    int cc = 4 * j;

    float4 num = make_float4(0.f, 0.f, 0.f, 0.f);
    float4 den = num;
    int cur = -1;
    float2 e01 = make_float2(0.f, 0.f), e23 = e01;

    int2 sdn = sds[w * 16];
    uint4 pdb = __ldg((const uint4*)(g_DB + (size_t)sdn.x * (2 * DD) + 8 * j));

    #pragma unroll
    for (int k = 0; k < 16; k++) {
        int lr = w * 16 + k;
        int2 sd = sdn;
        uint4 db = pdb;
        int pe = pes[lr];
        if (k < 15) {
            sdn = sds[lr + 1];
            pdb = __ldg((const uint4*)(g_DB + (size_t)sdn.x * (2 * DD) + 8 * j));
        }
        if (sd.y >= 0) {                        // valid edge (warp-uniform)
            if (sd.y != cur) {                  // run boundary (warp-uniform)
                if (cur >= 0) {
                    float* ndp = g_nd + (size_t)cur * (2 * DD) + 8 * j;
                    red_add_v4(ndp, num);
                    red_add_v4(ndp + 4, den);
                }
                cur = sd.y;
                num = make_float4(0.f, 0.f, 0.f, 0.f);
                den = num;
                uint2 ehu = __ldg((const uint2*)(g_Eh16 + (size_t)cur * DD + cc));
                e01 = h2f(ehu.x); e23 = h2f(ehu.y);
            }
            uint2 cu = *(uint2*)(Ch + csw16(lr, cc));
            float2 c01 = h2f(cu.x), c23 = h2f(cu.y);
            float2 d01 = h2f(db.x), d23 = h2f(db.y);
            float2 b01 = h2f(db.z), b23 = h2f(db.w);
            float4 x;
            x.x = c01.x + d01.x + e01.x;        // Dh includes bd + bc
            x.y = c01.y + d01.y + e01.y;
            x.z = c23.x + d23.x + e23.x;
            x.w = c23.y + d23.y + e23.y;
            __stcs((float4*)(out_e + (size_t)pe * DD + cc), x);
            float4 sg;
            sg.x = sigmoid_tanh(x.x);
            sg.y = sigmoid_tanh(x.y);
            sg.z = sigmoid_tanh(x.z);
            sg.w = sigmoid_tanh(x.w);
            num.x += sg.x * b01.x; num.y += sg.y * b01.y;
            num.z += sg.z * b23.x; num.w += sg.w * b23.y;
            den.x += sg.x; den.y += sg.y; den.z += sg.z; den.w += sg.w;
        }
    }
    if (cur >= 0) {
        float* ndp = g_nd + (size_t)cur * (2 * DD) + 8 * j;
        red_add_v4(ndp, num);
        red_add_v4(ndp + 4, den);
    }
}

// ---------------- finalize (deg>0 <=> den>0, sigmoids strictly positive) ----------------
__global__ void finalize_kernel(const float* __restrict__ h,
                                const float* __restrict__ norm,
                                float* __restrict__ out_h, int Nn) {
    int idx = blockIdx.x * blockDim.x + threadIdx.x;   // float4-block index
    int total = Nn * (DD / 4);
    if (idx >= total) return;
    int node = idx >> 5;
    int jj = idx & 31;
    float nm = __ldg(norm + node);
    const float* ndp = g_nd + (size_t)node * (2 * DD) + 8 * jj;
    float4 nu = *(const float4*)(ndp);
    float4 de = *(const float4*)(ndp + 4);
    float4 r;
    if (de.x > 0.f) {
        float4 a = ((const float4*)g_Ah)[idx];
        r.x = (a.x + nu.x / (de.x + 1e-6f)) * nm;
        r.y = (a.y + nu.y / (de.y + 1e-6f)) * nm;
        r.z = (a.z + nu.z / (de.z + 1e-6f)) * nm;
        r.w = (a.w + nu.w / (de.w + 1e-6f)) * nm;
    } else {
        float4 hh = *(const float4*)(h + (size_t)idx * 4);
        float sc = nm * nm;
        r = make_float4(hh.x * sc, hh.y * sc, hh.z * sc, hh.w * sc);
    }
    ((float4*)out_h)[idx] = r;
}

// ---------------- launch ----------------
extern "C" void kernel_launch(void* const* d_in, const int* in_sizes, int n_in,
                              void* d_out, int out_size) {
    const float* h    = (const float*)d_in[0];
    const float* e    = (const float*)d_in[1];
    const float* norm = (const float*)d_in[2];
    const int*   src  = (const int*)d_in[3];
    const int*   dst  = (const int*)d_in[4];
    const float* Wa = (const float*)d_in[5],  *ba = (const float*)d_in[6];
    const float* Wb = (const float*)d_in[7],  *bb = (const float*)d_in[8];
    const float* Wc = (const float*)d_in[9],  *bc = (const float*)d_in[10];
    const float* Wd = (const float*)d_in[11], *bd = (const float*)d_in[12];
    const float* We = (const float*)d_in[13], *be = (const float*)d_in[14];

    int Nn = in_sizes[0] / DD;   // 40000
    int Ee = in_sizes[3];        // 600000

    float* out_h = (float*)d_out;
    float* out_e = out_h + (size_t)Nn * DD;

    cudaFuncSetAttribute(node_mma_kernel, cudaFuncAttributeMaxDynamicSharedMemorySize, NSM_REQ);
    cudaFuncSetAttribute(edge_mma_kernel, cudaFuncAttributeMaxDynamicSharedMemorySize, ESM_REQ);

    prep_kernel<<<(5 * 16384 + 255) / 256, 256>>>(Wa, Wb, Wc, Wd, We, Nn);

    zero_hist_kernel<<<(Nn * (2 * DD / 4) + 255) / 256, 256>>>(dst, Nn, Ee);

    scan_kernel<<<1, 1024>>>(Nn);

    scatter_kernel<<<(Ee + 255) / 256, 256>>>(dst, Ee);

    dim3 ngrid((Nn + 127) / 128, 4);
    node_mma_kernel<<<ngrid, 256, NSM_REQ>>>(h, norm, ba, bb, bd, be, bc, Nn);

    edge_mma_kernel<<<(Ee + 127) / 128, 256, ESM_REQ>>>(e, src, dst, out_e, Ee);

    finalize_kernel<<<(Nn * (DD / 4) + 255) / 256, 256>>>(h, norm, out_h, Nn);
}